// round 14
// baseline (speedup 1.0000x reference)
#include <cuda_runtime.h>
#include <math.h>
#include <stdint.h>

#define Bb 256
#define Tt 128
#define Vv 512
#define Ee 64
#define Hh 256
#define G4 1024
#define KD 320
#define NB 128
#define NT 256

// ---------------- device scratch ----------------
__device__ __align__(16) float g_Gx[(size_t)Bb * Tt * G4];
__device__ __align__(16) float g_Xe[(size_t)Bb * Tt * Ee];
__device__ __align__(16) float g_WeT[Vv * Ee];
__device__ __align__(16) float g_WihTpE[Ee * G4];
__device__ __align__(16) float g_WhhTpE[Hh * G4];
__device__ __align__(16) float g_biasE[G4];
__device__ __align__(16) float g_WsTpD[KD * G4];
__device__ __align__(16) float g_biasD[G4];
__device__ __align__(16) float g_WoT[Hh * Vv];
__device__ __align__(16) float g_WdT[Vv * Ee];
__device__ __align__(16) float g_WdTb[Vv * Ee];
__device__ __align__(16) float g_emb[Bb * Ee];

// ---------------- helpers ----------------
__device__ __forceinline__ float ldcg(const float* p) {
    float v; asm volatile("ld.global.cg.f32 %0, [%1];" : "=f"(v) : "l"(p)); return v;
}
__device__ __forceinline__ float sigm(float x) { return 1.0f / (1.0f + expf(-x)); }

__device__ __forceinline__ uint32_t s2u(const void* p) {
    uint32_t a;
    asm("{ .reg .u64 t; cvta.to.shared.u64 t, %1; cvt.u32.u64 %0, t; }" : "=r"(a) : "l"(p));
    return a;
}
__device__ __forceinline__ void cluster_sync_() {
    asm volatile("barrier.cluster.arrive.aligned;" ::: "memory");
    asm volatile("barrier.cluster.wait.aligned;" ::: "memory");
}
__device__ __forceinline__ void st_clu_f32(uint32_t laddr, int rk, float v) {
    uint32_t ra;
    asm volatile("mapa.shared::cluster.u32 %0, %1, %2;" : "=r"(ra) : "r"(laddr), "r"(rk));
    asm volatile("st.shared::cluster.f32 [%0], %1;" :: "r"(ra), "f"(v));
}
__device__ __forceinline__ void st_clu_s32(uint32_t laddr, int rk, int v) {
    uint32_t ra;
    asm volatile("mapa.shared::cluster.u32 %0, %1, %2;" : "=r"(ra) : "r"(laddr), "r"(rk));
    asm volatile("st.shared::cluster.b32 [%0], %1;" :: "r"(ra), "r"(v));
}

// ---------------- pack weights (transpose + gate-interleave) ----------------
// packed col p: q = p&3 (i,f,g,o), j = p>>2 ; orig gate row = q*H + j
__global__ void pack_kernel(const float* __restrict__ We,
                            const float* __restrict__ Wih_e, const float* __restrict__ Whh_e,
                            const float* __restrict__ bih_e, const float* __restrict__ bhh_e,
                            const float* __restrict__ Wd, const float* __restrict__ bd,
                            const float* __restrict__ Wih_d, const float* __restrict__ Whh_d,
                            const float* __restrict__ bih_d, const float* __restrict__ bhh_d,
                            const float* __restrict__ Wo) {
    const int R0 = Hh * G4;         // WhhTpE
    const int R1 = R0 + Ee * G4;    // WihTpE
    const int R2 = R1 + KD * G4;    // WsTpD
    const int R3 = R2 + Hh * Vv;    // WoT
    const int R4 = R3 + Vv * Ee;    // WdT
    const int R5 = R4 + Vv * Ee;    // WdTb
    const int R6 = R5 + Vv * Ee;    // WeT
    const int R7 = R6 + G4;         // biasE
    const int R8 = R7 + G4;         // biasD
    for (int id = blockIdx.x * blockDim.x + threadIdx.x; id < R8; id += gridDim.x * blockDim.x) {
        if (id < R0) {
            int k = id / G4, p = id % G4, q = p & 3, j = p >> 2;
            g_WhhTpE[id] = Whh_e[(q * Hh + j) * Hh + k];
        } else if (id < R1) {
            int t = id - R0; int e = t / G4, p = t % G4, q = p & 3, j = p >> 2;
            g_WihTpE[t] = Wih_e[(q * Hh + j) * Ee + e];
        } else if (id < R2) {
            int t = id - R1; int k = t / G4, p = t % G4, q = p & 3, j = p >> 2;
            g_WsTpD[t] = (k < Ee) ? Wih_d[(q * Hh + j) * Ee + k]
                                  : Whh_d[(q * Hh + j) * Hh + (k - Ee)];
        } else if (id < R3) {
            int t = id - R2; int k = t / Vv, v = t % Vv;
            g_WoT[t] = Wo[v * Hh + k];
        } else if (id < R4) {
            int t = id - R3; int v = t / Ee, e = t % Ee;
            g_WdT[t] = Wd[e * Vv + v];
        } else if (id < R5) {
            int t = id - R4; int v = t / Ee, e = t % Ee;
            g_WdTb[t] = Wd[e * Vv + v] + bd[e];
        } else if (id < R6) {
            int t = id - R5; int v = t / Ee, e = t % Ee;
            g_WeT[t] = We[e * Vv + v];
        } else if (id < R7) {
            int p = id - R6, q = p & 3, j = p >> 2;
            g_biasE[p] = bih_e[q * Hh + j] + bhh_e[q * Hh + j];
        } else {
            int p = id - R7, q = p & 3, j = p >> 2;
            g_biasD[p] = bih_d[q * Hh + j] + bhh_d[q * Hh + j];
        }
    }
}

// ---------------- Xe = x @ We^T + be ----------------
__global__ void __launch_bounds__(256) xe_kernel(const float* __restrict__ x,
                                                 const float* __restrict__ be) {
    __shared__ float As[32][65];
    __shared__ float Bs[32][64];
    int tid = threadIdx.x;
    int tx = tid & 15, ty = tid >> 4;
    int m0 = blockIdx.x * 64;
    float acc[4][4];
#pragma unroll
    for (int c = 0; c < 4; c++) {
        float b = be[tx * 4 + c];
#pragma unroll
        for (int r = 0; r < 4; r++) acc[r][c] = b;
    }
    for (int kt = 0; kt < 16; ++kt) {
        int k0 = kt * 32;
        {
            int kk = tid & 31, mm = tid >> 5;
#pragma unroll
            for (int p = 0; p < 8; p++) {
                int m = mm + p * 8;
                As[kk][m] = x[(size_t)(m0 + m) * Vv + k0 + kk];
            }
        }
        {
            int ee = tid & 63, kk = tid >> 6;
#pragma unroll
            for (int p = 0; p < 8; p++) {
                int k = kk + p * 4;
                Bs[k][ee] = g_WeT[(size_t)(k0 + k) * Ee + ee];
            }
        }
        __syncthreads();
#pragma unroll
        for (int kk = 0; kk < 32; kk++) {
            float a[4], b[4];
#pragma unroll
            for (int r = 0; r < 4; r++) a[r] = As[kk][ty * 4 + r];
#pragma unroll
            for (int c = 0; c < 4; c++) b[c] = Bs[kk][tx * 4 + c];
#pragma unroll
            for (int r = 0; r < 4; r++)
#pragma unroll
                for (int c = 0; c < 4; c++) acc[r][c] += a[r] * b[c];
        }
        __syncthreads();
    }
#pragma unroll
    for (int r = 0; r < 4; r++) {
        int m = m0 + ty * 4 + r;
#pragma unroll
        for (int c = 0; c < 4; c++) g_Xe[(size_t)m * Ee + tx * 4 + c] = acc[r][c];
    }
}

// ---------------- Gx = Xe @ WihTpE + biasE  (output [t][b][1024]) ----------------
__global__ void __launch_bounds__(256) gx_kernel() {
    __shared__ float As[64][65];
    __shared__ float Bs[64][64];
    int tid = threadIdx.x;
    int tx = tid & 15, ty = tid >> 4;
    int m0 = blockIdx.x * 64;
    int n0 = blockIdx.y * 64;
    {
        int kk = tid & 63, mm = tid >> 6;
#pragma unroll
        for (int p = 0; p < 16; p++) {
            int m = mm + p * 4;
            As[kk][m] = g_Xe[(size_t)(m0 + m) * Ee + kk];
        }
    }
    {
        int nn = tid & 63, kk = tid >> 6;
#pragma unroll
        for (int p = 0; p < 16; p++) {
            int k = kk + p * 4;
            Bs[k][nn] = g_WihTpE[(size_t)k * G4 + n0 + nn];
        }
    }
    __syncthreads();
    float acc[4][4];
#pragma unroll
    for (int c = 0; c < 4; c++) {
        float b = g_biasE[n0 + tx * 4 + c];
#pragma unroll
        for (int r = 0; r < 4; r++) acc[r][c] = b;
    }
#pragma unroll
    for (int kk = 0; kk < 64; kk++) {
        float a[4], b[4];
#pragma unroll
        for (int r = 0; r < 4; r++) a[r] = As[kk][ty * 4 + r];
#pragma unroll
        for (int c = 0; c < 4; c++) b[c] = Bs[kk][tx * 4 + c];
#pragma unroll
        for (int r = 0; r < 4; r++)
#pragma unroll
            for (int c = 0; c < 4; c++) acc[r][c] += a[r] * b[c];
    }
#pragma unroll
    for (int r = 0; r < 4; r++) {
        int bt = m0 + ty * 4 + r;
        int b = bt >> 7, t = bt & 127;
        size_t base = ((size_t)t * Bb + b) * G4 + n0 + tx * 4;
#pragma unroll
        for (int c = 0; c < 4; c++) g_Gx[base + c] = acc[r][c];
    }
}

// ---------------- emb0 ----------------
__global__ void emb0_kernel(const float* __restrict__ x, const float* __restrict__ bd) {
    __shared__ float x0[Vv];
    int b = blockIdx.x, tid = threadIdx.x; // 64 threads
    for (int i = tid; i < Vv; i += 64) x0[i] = x[(size_t)b * Tt * Vv + i];
    __syncthreads();
    float acc = bd[tid];
    for (int v = 0; v < Vv; v++) acc += x0[v] * g_WdT[(size_t)v * Ee + tid];
    g_emb[b * Ee + tid] = acc;
}

// ---------------- init: y[:,0,:]=0, x_lens passthrough ----------------
__global__ void init_kernel(const int* __restrict__ xlens, float* __restrict__ out,
                            int write_extra) {
    int id = blockIdx.x * blockDim.x + threadIdx.x;
    if (id < Bb * Vv) {
        int b = id / Vv, v = id % Vv;
        out[(size_t)b * Tt * Vv + v] = 0.f;
    }
    if (write_extra && id < Bb) out[(size_t)Bb * Tt * Vv + id] = (float)xlens[id];
}

// ---------------- persistent-free cluster recurrent kernel ----------------
// cluster of 4 CTAs owns 8 batch rows. CTA rank r: packed gate cols [256r,256r+256),
// i.e. h units [64r, 64r+64), for all 8 rows. warp w = row w, lane l = units 2l,2l+1.
__global__ void __cluster_dims__(4, 1, 1) __launch_bounds__(NT, 1)
rec_kernel(const int* __restrict__ xlens, const float* __restrict__ bo,
           float* __restrict__ out, int write_extra) {
    __shared__ float sh_h[2][8][264];
    __shared__ float sh_emb[8][66];
    __shared__ float sh_av[4][8];
    __shared__ int   sh_ai[4][8];

    const int tid = threadIdx.x;
    const int w = tid >> 5, l = tid & 31;
    uint32_t rank_u; asm("mov.u32 %0, %%cluster_ctarank;" : "=r"(rank_u));
    const int rank = (int)rank_u;
    const int clus = blockIdx.x >> 2;
    const int b0 = clus * 8;
    const int row = b0 + w;
    const int c8 = rank * 256 + 8 * l;     // this thread's 8 packed cols
    const int u0 = rank * 64 + 2 * l;      // owned h units
    const unsigned FULL = 0xffffffffu;

    // zero h buffer 0 (read at step 0)
    for (int i = tid; i < 8 * 264; i += NT) ((float*)sh_h[0])[i] = 0.f;
    __syncthreads();
    cluster_sync_();

    const int len = xlens[row];
    float c0 = 0.f, c1 = 0.f, h0 = 0.f, h1 = 0.f;
    int par = 0;

    float4 ga = __ldg((const float4*)&g_Gx[(size_t)row * G4 + c8]);
    float4 gb = __ldg((const float4*)&g_Gx[(size_t)row * G4 + c8 + 4]);

    // ======================= encoder =======================
    for (int t = 0; t < Tt; ++t) {
        float acc[8] = {ga.x, ga.y, ga.z, ga.w, gb.x, gb.y, gb.z, gb.w};
        const float* hc = sh_h[par][w];
#pragma unroll 8
        for (int k = 0; k < Hh; ++k) {
            float hk = hc[k];
            float4 w0 = __ldg((const float4*)&g_WhhTpE[(size_t)k * G4 + c8]);
            float4 w1 = __ldg((const float4*)&g_WhhTpE[(size_t)k * G4 + c8 + 4]);
            acc[0] += hk * w0.x; acc[1] += hk * w0.y; acc[2] += hk * w0.z; acc[3] += hk * w0.w;
            acc[4] += hk * w1.x; acc[5] += hk * w1.y; acc[6] += hk * w1.z; acc[7] += hk * w1.w;
        }
        {
            bool m = (t < len);
            float i_ = sigm(acc[0]), f_ = sigm(acc[1]), g_ = tanhf(acc[2]), o_ = sigm(acc[3]);
            float cn = f_ * c0 + i_ * g_;
            float hn = o_ * tanhf(cn);
            c0 = m ? cn : c0; h0 = m ? hn : h0;
            i_ = sigm(acc[4]); f_ = sigm(acc[5]); g_ = tanhf(acc[6]); o_ = sigm(acc[7]);
            cn = f_ * c1 + i_ * g_;
            hn = o_ * tanhf(cn);
            c1 = m ? cn : c1; h1 = m ? hn : h1;
        }
        if (t + 1 < Tt) {
            const float* gx = g_Gx + ((size_t)(t + 1) * Bb + row) * G4;
            ga = __ldg((const float4*)&gx[c8]);
            gb = __ldg((const float4*)&gx[c8 + 4]);
        }
        // broadcast my 2 h units (for my row) to all 4 CTAs' next buffer
        {
            uint32_t la = s2u(&sh_h[par ^ 1][w][u0]);
#pragma unroll
            for (int rk = 0; rk < 4; rk++) {
                st_clu_f32(la, rk, h0);
                st_clu_f32(la + 4, rk, h1);
            }
        }
        cluster_sync_();
        par ^= 1;
    }

    if (write_extra) {
        size_t eb = (size_t)Bb * Tt * Vv + Bb + (size_t)row * Hh + u0;
        out[eb] = h0;
        out[eb + 1] = h1;
    }

    // ---- decoder constants ----
    float4 bda = __ldg((const float4*)&g_biasD[c8]);
    float4 bdb = __ldg((const float4*)&g_biasD[c8 + 4]);
    const int lc = rank * 128 + 4 * l;     // this thread's 4 vocab cols
    float4 bo4 = __ldg((const float4*)&bo[lc]);

    // emb for step 0
    {
        sh_emb[w][2 * l]     = ldcg(&g_emb[(size_t)row * Ee + 2 * l]);
        sh_emb[w][2 * l + 1] = ldcg(&g_emb[(size_t)row * Ee + 2 * l + 1]);
        __syncwarp();
    }

    // ======================= decoder =======================
    for (int s = 0; s < Tt - 1; ++s) {
        float acc[8] = {bda.x, bda.y, bda.z, bda.w, bdb.x, bdb.y, bdb.z, bdb.w};
        {
            const float* eb = sh_emb[w];
#pragma unroll 8
            for (int k = 0; k < Ee; ++k) {
                float ek = eb[k];
                float4 w0 = __ldg((const float4*)&g_WsTpD[(size_t)k * G4 + c8]);
                float4 w1 = __ldg((const float4*)&g_WsTpD[(size_t)k * G4 + c8 + 4]);
                acc[0] += ek * w0.x; acc[1] += ek * w0.y; acc[2] += ek * w0.z; acc[3] += ek * w0.w;
                acc[4] += ek * w1.x; acc[5] += ek * w1.y; acc[6] += ek * w1.z; acc[7] += ek * w1.w;
            }
        }
        {
            const float* hc = sh_h[par][w];
#pragma unroll 8
            for (int k = 0; k < Hh; ++k) {
                float hk = hc[k];
                float4 w0 = __ldg((const float4*)&g_WsTpD[(size_t)(k + Ee) * G4 + c8]);
                float4 w1 = __ldg((const float4*)&g_WsTpD[(size_t)(k + Ee) * G4 + c8 + 4]);
                acc[0] += hk * w0.x; acc[1] += hk * w0.y; acc[2] += hk * w0.z; acc[3] += hk * w0.w;
                acc[4] += hk * w1.x; acc[5] += hk * w1.y; acc[6] += hk * w1.z; acc[7] += hk * w1.w;
            }
        }
        {
            float i_ = sigm(acc[0]), f_ = sigm(acc[1]), g_ = tanhf(acc[2]), o_ = sigm(acc[3]);
            c0 = f_ * c0 + i_ * g_;
            h0 = o_ * tanhf(c0);
            i_ = sigm(acc[4]); f_ = sigm(acc[5]); g_ = tanhf(acc[6]); o_ = sigm(acc[7]);
            c1 = f_ * c1 + i_ * g_;
            h1 = o_ * tanhf(c1);
        }
        {
            uint32_t la = s2u(&sh_h[par ^ 1][w][u0]);
#pragma unroll
            for (int rk = 0; rk < 4; rk++) {
                st_clu_f32(la, rk, h0);
                st_clu_f32(la + 4, rk, h1);
            }
        }
        cluster_sync_();
        par ^= 1;

        // ---- logits: 4 vocab cols per thread, row = warp ----
        float a0 = bo4.x, a1 = bo4.y, a2 = bo4.z, a3 = bo4.w;
        {
            const float* hc = sh_h[par][w];
#pragma unroll 8
            for (int k = 0; k < Hh; ++k) {
                float hk = hc[k];
                float4 wo = __ldg((const float4*)&g_WoT[(size_t)k * Vv + lc]);
                a0 += hk * wo.x; a1 += hk * wo.y; a2 += hk * wo.z; a3 += hk * wo.w;
            }
        }
        {
            size_t yb = (size_t)row * Tt * Vv + (size_t)(s + 1) * Vv + lc;
            out[yb] = a0; out[yb + 1] = a1; out[yb + 2] = a2; out[yb + 3] = a3;
        }
        // argmax: local 4 cols (first-max), then warp reduce (128 cols of this rank)
        float v = a0; int ix = lc;
        if (a1 > v) { v = a1; ix = lc + 1; }
        if (a2 > v) { v = a2; ix = lc + 2; }
        if (a3 > v) { v = a3; ix = lc + 3; }
#pragma unroll
        for (int off = 16; off > 0; off >>= 1) {
            float ov = __shfl_down_sync(FULL, v, off);
            int oi = __shfl_down_sync(FULL, ix, off);
            if (ov > v || (ov == v && oi < ix)) { v = ov; ix = oi; }
        }
        if (l == 0) {
            uint32_t lav = s2u(&sh_av[rank][w]);
            uint32_t lai = s2u(&sh_ai[rank][w]);
#pragma unroll
            for (int rk = 0; rk < 4; rk++) {
                st_clu_f32(lav, rk, v);
                st_clu_s32(lai, rk, ix);
            }
        }
        cluster_sync_();
        // combine 4 rank partials (all lanes, redundantly; ranks ascend in col order)
        float bv = sh_av[0][w]; int bi = sh_ai[0][w];
#pragma unroll
        for (int rk = 1; rk < 4; rk++) {
            float vv = sh_av[rk][w]; int ii = sh_ai[rk][w];
            if (vv > bv) { bv = vv; bi = ii; }
        }
        // gather next emb for my row (warp-local)
        sh_emb[w][2 * l]     = __ldg(&g_WdTb[(size_t)bi * Ee + 2 * l]);
        sh_emb[w][2 * l + 1] = __ldg(&g_WdTb[(size_t)bi * Ee + 2 * l + 1]);
        __syncwarp();
    }
}

// ---------------- launch ----------------
extern "C" void kernel_launch(void* const* d_in, const int* in_sizes, int n_in,
                              void* d_out, int out_size) {
    (void)in_sizes; (void)n_in;
    const float* x     = (const float*)d_in[0];
    const int*   xlens = (const int*)  d_in[1];
    const float* We    = (const float*)d_in[2];
    const float* be    = (const float*)d_in[3];
    const float* Wih_e = (const float*)d_in[4];
    const float* Whh_e = (const float*)d_in[5];
    const float* bih_e = (const float*)d_in[6];
    const float* bhh_e = (const float*)d_in[7];
    const float* Wd    = (const float*)d_in[8];
    const float* bd    = (const float*)d_in[9];
    const float* Wih_d = (const float*)d_in[10];
    const float* Whh_d = (const float*)d_in[11];
    const float* bih_d = (const float*)d_in[12];
    const float* bhh_d = (const float*)d_in[13];
    const float* Wo    = (const float*)d_in[14];
    const float* bo    = (const float*)d_in[15];
    float* out = (float*)d_out;

    int write_extra = (out_size >= Bb * Tt * Vv + Bb + Bb * Hh) ? 1 : 0;

    pack_kernel<<<1024, 256>>>(We, Wih_e, Whh_e, bih_e, bhh_e,
                               Wd, bd, Wih_d, Whh_d, bih_d, bhh_d, Wo);
    xe_kernel<<<512, 256>>>(x, be);
    gx_kernel<<<dim3(512, 16), 256>>>();
    emb0_kernel<<<Bb, 64>>>(x, bd);
    init_kernel<<<512, 256>>>(xlens, out, write_extra);
    rec_kernel<<<NB, NT>>>(xlens, bo, out, write_extra);
}

// round 15
// speedup vs baseline: 1.1287x; 1.1287x over previous
#include <cuda_runtime.h>
#include <math.h>
#include <stdint.h>

#define Bb 256
#define Tt 128
#define Vv 512
#define Ee 64
#define Hh 256
#define G4 1024
#define KD 320
#define NB 128
#define NT 256
#define CL 8            // cluster size
#define CROWS 16        // batch rows per cluster

// dynamic smem layout (floats)
#define WS_OFF 0
#define WS_FLOATS (KD * 128)                 // 40960 (enc uses first 256 rows)
#define HS_OFF WS_FLOATS                     // 40960
#define HS_FLOATS (2 * CROWS * 256)          // 8192
#define EM_OFF (HS_OFF + HS_FLOATS)          // 49152
#define EM_FLOATS (CROWS * 64)               // 1024
#define AV_OFF (EM_OFF + EM_FLOATS)          // 50176
#define AI_OFF (AV_OFF + 128)                // 50304
#define BI_OFF (AI_OFF + 128)                // 50432
#define DSM_FLOATS (BI_OFF + 16)             // 50448
#define DSM_BYTES (DSM_FLOATS * 4)           // 201792

// ---------------- device scratch ----------------
__device__ __align__(16) float g_Gx[(size_t)Bb * Tt * G4];
__device__ __align__(16) float g_Xe[(size_t)Bb * Tt * Ee];
__device__ __align__(16) float g_WeT[Vv * Ee];
__device__ __align__(16) float g_WihTpE[Ee * G4];
__device__ __align__(16) float g_WhhTpE[Hh * G4];
__device__ __align__(16) float g_biasE[G4];
__device__ __align__(16) float g_WsTpD[KD * G4];
__device__ __align__(16) float g_biasD[G4];
__device__ __align__(16) float g_WoT[Hh * Vv];
__device__ __align__(16) float g_WdT[Vv * Ee];
__device__ __align__(16) float g_WdTb[Vv * Ee];
__device__ __align__(16) float g_emb[Bb * Ee];

// ---------------- helpers ----------------
__device__ __forceinline__ float sigm(float x) { return 1.0f / (1.0f + expf(-x)); }

__device__ __forceinline__ uint32_t s2u(const void* p) {
    uint32_t a;
    asm("{ .reg .u64 t; cvta.to.shared.u64 t, %1; cvt.u32.u64 %0, t; }" : "=r"(a) : "l"(p));
    return a;
}
__device__ __forceinline__ void cluster_sync_() {
    asm volatile("barrier.cluster.arrive.aligned;" ::: "memory");
    asm volatile("barrier.cluster.wait.aligned;" ::: "memory");
}
__device__ __forceinline__ void st_clu_f32(uint32_t laddr, int rk, float v) {
    uint32_t ra;
    asm volatile("mapa.shared::cluster.u32 %0, %1, %2;" : "=r"(ra) : "r"(laddr), "r"(rk));
    asm volatile("st.shared::cluster.f32 [%0], %1;" :: "r"(ra), "f"(v));
}
__device__ __forceinline__ void st_clu_s32(uint32_t laddr, int rk, int v) {
    uint32_t ra;
    asm volatile("mapa.shared::cluster.u32 %0, %1, %2;" : "=r"(ra) : "r"(laddr), "r"(rk));
    asm volatile("st.shared::cluster.b32 [%0], %1;" :: "r"(ra), "r"(v));
}

// ---------------- pack weights (transpose + gate-interleave) ----------------
// packed col p: q = p&3 (i,f,g,o), j = p>>2 ; orig gate row = q*H + j
__global__ void pack_kernel(const float* __restrict__ We,
                            const float* __restrict__ Wih_e, const float* __restrict__ Whh_e,
                            const float* __restrict__ bih_e, const float* __restrict__ bhh_e,
                            const float* __restrict__ Wd, const float* __restrict__ bd,
                            const float* __restrict__ Wih_d, const float* __restrict__ Whh_d,
                            const float* __restrict__ bih_d, const float* __restrict__ bhh_d,
                            const float* __restrict__ Wo) {
    const int R0 = Hh * G4;         // WhhTpE
    const int R1 = R0 + Ee * G4;    // WihTpE
    const int R2 = R1 + KD * G4;    // WsTpD
    const int R3 = R2 + Hh * Vv;    // WoT
    const int R4 = R3 + Vv * Ee;    // WdT
    const int R5 = R4 + Vv * Ee;    // WdTb
    const int R6 = R5 + Vv * Ee;    // WeT
    const int R7 = R6 + G4;         // biasE
    const int R8 = R7 + G4;         // biasD
    for (int id = blockIdx.x * blockDim.x + threadIdx.x; id < R8; id += gridDim.x * blockDim.x) {
        if (id < R0) {
            int k = id / G4, p = id % G4, q = p & 3, j = p >> 2;
            g_WhhTpE[id] = Whh_e[(q * Hh + j) * Hh + k];
        } else if (id < R1) {
            int t = id - R0; int e = t / G4, p = t % G4, q = p & 3, j = p >> 2;
            g_WihTpE[t] = Wih_e[(q * Hh + j) * Ee + e];
        } else if (id < R2) {
            int t = id - R1; int k = t / G4, p = t % G4, q = p & 3, j = p >> 2;
            g_WsTpD[t] = (k < Ee) ? Wih_d[(q * Hh + j) * Ee + k]
                                  : Whh_d[(q * Hh + j) * Hh + (k - Ee)];
        } else if (id < R3) {
            int t = id - R2; int k = t / Vv, v = t % Vv;
            g_WoT[t] = Wo[v * Hh + k];
        } else if (id < R4) {
            int t = id - R3; int v = t / Ee, e = t % Ee;
            g_WdT[t] = Wd[e * Vv + v];
        } else if (id < R5) {
            int t = id - R4; int v = t / Ee, e = t % Ee;
            g_WdTb[t] = Wd[e * Vv + v] + bd[e];
        } else if (id < R6) {
            int t = id - R5; int v = t / Ee, e = t % Ee;
            g_WeT[t] = We[e * Vv + v];
        } else if (id < R7) {
            int p = id - R6, q = p & 3, j = p >> 2;
            g_biasE[p] = bih_e[q * Hh + j] + bhh_e[q * Hh + j];
        } else {
            int p = id - R7, q = p & 3, j = p >> 2;
            g_biasD[p] = bih_d[q * Hh + j] + bhh_d[q * Hh + j];
        }
    }
}

// ---------------- Xe = x @ We^T + be ----------------
__global__ void __launch_bounds__(256) xe_kernel(const float* __restrict__ x,
                                                 const float* __restrict__ be) {
    __shared__ float As[32][65];
    __shared__ float Bs[32][64];
    int tid = threadIdx.x;
    int tx = tid & 15, ty = tid >> 4;
    int m0 = blockIdx.x * 64;
    float acc[4][4];
#pragma unroll
    for (int c = 0; c < 4; c++) {
        float b = be[tx * 4 + c];
#pragma unroll
        for (int r = 0; r < 4; r++) acc[r][c] = b;
    }
    for (int kt = 0; kt < 16; ++kt) {
        int k0 = kt * 32;
        {
            int kk = tid & 31, mm = tid >> 5;
#pragma unroll
            for (int p = 0; p < 8; p++) {
                int m = mm + p * 8;
                As[kk][m] = x[(size_t)(m0 + m) * Vv + k0 + kk];
            }
        }
        {
            int ee = tid & 63, kk = tid >> 6;
#pragma unroll
            for (int p = 0; p < 8; p++) {
                int k = kk + p * 4;
                Bs[k][ee] = g_WeT[(size_t)(k0 + k) * Ee + ee];
            }
        }
        __syncthreads();
#pragma unroll
        for (int kk = 0; kk < 32; kk++) {
            float a[4], b[4];
#pragma unroll
            for (int r = 0; r < 4; r++) a[r] = As[kk][ty * 4 + r];
#pragma unroll
            for (int c = 0; c < 4; c++) b[c] = Bs[kk][tx * 4 + c];
#pragma unroll
            for (int r = 0; r < 4; r++)
#pragma unroll
                for (int c = 0; c < 4; c++) acc[r][c] += a[r] * b[c];
        }
        __syncthreads();
    }
#pragma unroll
    for (int r = 0; r < 4; r++) {
        int m = m0 + ty * 4 + r;
#pragma unroll
        for (int c = 0; c < 4; c++) g_Xe[(size_t)m * Ee + tx * 4 + c] = acc[r][c];
    }
}

// ---------------- Gx = Xe @ WihTpE + biasE  (output [t][b][1024]) ----------------
__global__ void __launch_bounds__(256) gx_kernel() {
    __shared__ float As[64][65];
    __shared__ float Bs[64][64];
    int tid = threadIdx.x;
    int tx = tid & 15, ty = tid >> 4;
    int m0 = blockIdx.x * 64;
    int n0 = blockIdx.y * 64;
    {
        int kk = tid & 63, mm = tid >> 6;
#pragma unroll
        for (int p = 0; p < 16; p++) {
            int m = mm + p * 4;
            As[kk][m] = g_Xe[(size_t)(m0 + m) * Ee + kk];
        }
    }
    {
        int nn = tid & 63, kk = tid >> 6;
#pragma unroll
        for (int p = 0; p < 16; p++) {
            int k = kk + p * 4;
            Bs[k][nn] = g_WihTpE[(size_t)k * G4 + n0 + nn];
        }
    }
    __syncthreads();
    float acc[4][4];
#pragma unroll
    for (int c = 0; c < 4; c++) {
        float b = g_biasE[n0 + tx * 4 + c];
#pragma unroll
        for (int r = 0; r < 4; r++) acc[r][c] = b;
    }
#pragma unroll
    for (int kk = 0; kk < 64; kk++) {
        float a[4], b[4];
#pragma unroll
        for (int r = 0; r < 4; r++) a[r] = As[kk][ty * 4 + r];
#pragma unroll
        for (int c = 0; c < 4; c++) b[c] = Bs[kk][tx * 4 + c];
#pragma unroll
        for (int r = 0; r < 4; r++)
#pragma unroll
            for (int c = 0; c < 4; c++) acc[r][c] += a[r] * b[c];
    }
#pragma unroll
    for (int r = 0; r < 4; r++) {
        int bt = m0 + ty * 4 + r;
        int b = bt >> 7, t = bt & 127;
        size_t base = ((size_t)t * Bb + b) * G4 + n0 + tx * 4;
#pragma unroll
        for (int c = 0; c < 4; c++) g_Gx[base + c] = acc[r][c];
    }
}

// ---------------- emb0 ----------------
__global__ void emb0_kernel(const float* __restrict__ x, const float* __restrict__ bd) {
    __shared__ float x0[Vv];
    int b = blockIdx.x, tid = threadIdx.x; // 64 threads
    for (int i = tid; i < Vv; i += 64) x0[i] = x[(size_t)b * Tt * Vv + i];
    __syncthreads();
    float acc = bd[tid];
    for (int v = 0; v < Vv; v++) acc += x0[v] * g_WdT[(size_t)v * Ee + tid];
    g_emb[b * Ee + tid] = acc;
}

// ---------------- init: y[:,0,:]=0, x_lens passthrough ----------------
__global__ void init_kernel(const int* __restrict__ xlens, float* __restrict__ out,
                            int write_extra) {
    int id = blockIdx.x * blockDim.x + threadIdx.x;
    if (id < Bb * Vv) {
        int b = id / Vv, v = id % Vv;
        out[(size_t)b * Tt * Vv + v] = 0.f;
    }
    if (write_extra && id < Bb) out[(size_t)Bb * Tt * Vv + id] = (float)xlens[id];
}

// ---------------- cluster recurrent kernel ----------------
// cluster of 8 CTAs owns 16 batch rows; rank owns packed gate cols [128r,128r+128).
// thread: tx = tid&31 -> 4 cols (one unit's i,f,g,o), ty = tid>>5 -> rows 2ty,2ty+1.
__global__ void __cluster_dims__(CL, 1, 1) __launch_bounds__(NT, 1)
rec_kernel(const int* __restrict__ xlens, const float* __restrict__ bo,
           float* __restrict__ out, int write_extra) {
    extern __shared__ float dsm[];
    float* Ws  = dsm + WS_OFF;   // [320][128]
    float* hsb = dsm + HS_OFF;   // [2][16][256]
    float* emS = dsm + EM_OFF;   // [16][64]
    float* avS = dsm + AV_OFF;   // [8][16]
    int*   aiS = (int*)(dsm + AI_OFF);  // [8][16]
    int*   biS = (int*)(dsm + BI_OFF);  // [16]

    const int tid = threadIdx.x;
    const int tx = tid & 31, ty = tid >> 5;
    uint32_t rank_u; asm("mov.u32 %0, %%cluster_ctarank;" : "=r"(rank_u));
    const int rank = (int)rank_u;
    const int clus = blockIdx.x >> 3;
    const int lr0 = 2 * ty, lr1 = lr0 + 1;          // local rows
    const int gr0 = clus * CROWS + lr0, gr1 = gr0 + 1;
    const int c4 = rank * 128 + 4 * tx;             // global packed cols
    const int u = rank * 32 + tx;                   // owned h unit
    const unsigned FULL = 0xffffffffu;

    // ---- stage encoder Whh slice [256][128] ----
    for (int i = tid; i < 256 * 32; i += NT) {
        int k = i >> 5, c = (i & 31) * 4;
        *(float4*)&Ws[k * 128 + c] =
            *(const float4*)&g_WhhTpE[(size_t)k * G4 + rank * 128 + c];
    }
    // zero h buffer 0
    for (int i = tid; i < CROWS * 256; i += NT) hsb[i] = 0.f;
    __syncthreads();
    cluster_sync_();

    const int len0 = xlens[gr0], len1 = xlens[gr1];
    float c0 = 0.f, c1 = 0.f, h0v = 0.f, h1v = 0.f;
    int par = 0;

    float4 ga = __ldg((const float4*)&g_Gx[(size_t)gr0 * G4 + c4]);
    float4 gb = __ldg((const float4*)&g_Gx[(size_t)gr1 * G4 + c4]);

    // ======================= encoder =======================
    for (int t = 0; t < Tt; ++t) {
        float a0[4] = {ga.x, ga.y, ga.z, ga.w};
        float a1[4] = {gb.x, gb.y, gb.z, gb.w};
        const float* h0p = hsb + par * (CROWS * 256) + lr0 * 256;
        const float* h1p = h0p + 256;
#pragma unroll 8
        for (int kc = 0; kc < 64; ++kc) {
            float4 hh0 = *(const float4*)&h0p[kc * 4];
            float4 hh1 = *(const float4*)&h1p[kc * 4];
#pragma unroll
            for (int j = 0; j < 4; ++j) {
                float4 w = *(const float4*)&Ws[(kc * 4 + j) * 128 + 4 * tx];
                float e0 = (j == 0) ? hh0.x : (j == 1) ? hh0.y : (j == 2) ? hh0.z : hh0.w;
                float e1 = (j == 0) ? hh1.x : (j == 1) ? hh1.y : (j == 2) ? hh1.z : hh1.w;
                a0[0] += e0 * w.x; a0[1] += e0 * w.y; a0[2] += e0 * w.z; a0[3] += e0 * w.w;
                a1[0] += e1 * w.x; a1[1] += e1 * w.y; a1[2] += e1 * w.z; a1[3] += e1 * w.w;
            }
        }
        {
            bool m = (t < len0);
            float i_ = sigm(a0[0]), f_ = sigm(a0[1]), g_ = tanhf(a0[2]), o_ = sigm(a0[3]);
            float cn = f_ * c0 + i_ * g_;
            float hn = o_ * tanhf(cn);
            c0 = m ? cn : c0; h0v = m ? hn : h0v;
            m = (t < len1);
            i_ = sigm(a1[0]); f_ = sigm(a1[1]); g_ = tanhf(a1[2]); o_ = sigm(a1[3]);
            cn = f_ * c1 + i_ * g_;
            hn = o_ * tanhf(cn);
            c1 = m ? cn : c1; h1v = m ? hn : h1v;
        }
        if (t + 1 < Tt) {
            const float* gx = g_Gx + ((size_t)(t + 1) * Bb) * G4;
            ga = __ldg((const float4*)&gx[(size_t)gr0 * G4 + c4]);
            gb = __ldg((const float4*)&gx[(size_t)gr1 * G4 + c4]);
        }
        {
            uint32_t la0 = s2u(&hsb[(par ^ 1) * (CROWS * 256) + lr0 * 256 + u]);
            uint32_t la1 = la0 + 256 * 4;
#pragma unroll
            for (int rk = 0; rk < CL; rk++) {
                st_clu_f32(la0, rk, h0v);
                st_clu_f32(la1, rk, h1v);
            }
        }
        cluster_sync_();
        par ^= 1;
    }

    if (write_extra) {
        size_t eb = (size_t)Bb * Tt * Vv + Bb;
        out[eb + (size_t)gr0 * Hh + u] = h0v;
        out[eb + (size_t)gr1 * Hh + u] = h1v;
    }

    // ---- stage decoder stacked weight slice [320][128] + emb + constants ----
    __syncthreads();
    for (int i = tid; i < KD * 32; i += NT) {
        int k = i >> 5, c = (i & 31) * 4;
        *(float4*)&Ws[k * 128 + c] =
            *(const float4*)&g_WsTpD[(size_t)k * G4 + rank * 128 + c];
    }
    {
        int row = tid >> 4, c = (tid & 15) * 4;
        *(float4*)&emS[row * 64 + c] =
            __ldg((const float4*)&g_emb[(size_t)(clus * CROWS + row) * Ee + c]);
    }
    const float4 bd4 = __ldg((const float4*)&g_biasD[c4]);
    const int gc = rank * 64 + 2 * tx;     // logits: 2 vocab cols
    const float bo0 = bo[gc], bo1 = bo[gc + 1];
    __syncthreads();

    // ======================= decoder =======================
    for (int s = 0; s < Tt - 1; ++s) {
        float a0[4] = {bd4.x, bd4.y, bd4.z, bd4.w};
        float a1[4] = {bd4.x, bd4.y, bd4.z, bd4.w};
        // emb part: k in [0,64)
        {
            const float* e0p = emS + lr0 * 64;
            const float* e1p = e0p + 64;
#pragma unroll 4
            for (int kc = 0; kc < 16; ++kc) {
                float4 hh0 = *(const float4*)&e0p[kc * 4];
                float4 hh1 = *(const float4*)&e1p[kc * 4];
#pragma unroll
                for (int j = 0; j < 4; ++j) {
                    float4 w = *(const float4*)&Ws[(kc * 4 + j) * 128 + 4 * tx];
                    float e0 = (j == 0) ? hh0.x : (j == 1) ? hh0.y : (j == 2) ? hh0.z : hh0.w;
                    float e1 = (j == 0) ? hh1.x : (j == 1) ? hh1.y : (j == 2) ? hh1.z : hh1.w;
                    a0[0] += e0 * w.x; a0[1] += e0 * w.y; a0[2] += e0 * w.z; a0[3] += e0 * w.w;
                    a1[0] += e1 * w.x; a1[1] += e1 * w.y; a1[2] += e1 * w.z; a1[3] += e1 * w.w;
                }
            }
        }
        // h part: k in [64,320)
        {
            const float* h0p = hsb + par * (CROWS * 256) + lr0 * 256;
            const float* h1p = h0p + 256;
#pragma unroll 8
            for (int kc = 0; kc < 64; ++kc) {
                float4 hh0 = *(const float4*)&h0p[kc * 4];
                float4 hh1 = *(const float4*)&h1p[kc * 4];
#pragma unroll
                for (int j = 0; j < 4; ++j) {
                    float4 w = *(const float4*)&Ws[(64 + kc * 4 + j) * 128 + 4 * tx];
                    float e0 = (j == 0) ? hh0.x : (j == 1) ? hh0.y : (j == 2) ? hh0.z : hh0.w;
                    float e1 = (j == 0) ? hh1.x : (j == 1) ? hh1.y : (j == 2) ? hh1.z : hh1.w;
                    a0[0] += e0 * w.x; a0[1] += e0 * w.y; a0[2] += e0 * w.z; a0[3] += e0 * w.w;
                    a1[0] += e1 * w.x; a1[1] += e1 * w.y; a1[2] += e1 * w.z; a1[3] += e1 * w.w;
                }
            }
        }
        {
            float i_ = sigm(a0[0]), f_ = sigm(a0[1]), g_ = tanhf(a0[2]), o_ = sigm(a0[3]);
            c0 = f_ * c0 + i_ * g_;
            h0v = o_ * tanhf(c0);
            i_ = sigm(a1[0]); f_ = sigm(a1[1]); g_ = tanhf(a1[2]); o_ = sigm(a1[3]);
            c1 = f_ * c1 + i_ * g_;
            h1v = o_ * tanhf(c1);
        }
        {
            uint32_t la0 = s2u(&hsb[(par ^ 1) * (CROWS * 256) + lr0 * 256 + u]);
            uint32_t la1 = la0 + 256 * 4;
#pragma unroll
            for (int rk = 0; rk < CL; rk++) {
                st_clu_f32(la0, rk, h0v);
                st_clu_f32(la1, rk, h1v);
            }
        }
        cluster_sync_();
        par ^= 1;

        // ---- logits: 2 rows x 2 vocab cols per thread (Wo via L1) ----
        {
            const float* hq0 = hsb + par * (CROWS * 256) + lr0 * 256;
            const float* hq1 = hq0 + 256;
            float l0 = bo0, l1 = bo1, m0 = bo0, m1 = bo1;
#pragma unroll 8
            for (int k = 0; k < Hh; ++k) {
                float2 w = __ldg((const float2*)&g_WoT[(size_t)k * Vv + gc]);
                float hk0 = hq0[k], hk1 = hq1[k];
                l0 += hk0 * w.x; l1 += hk0 * w.y;
                m0 += hk1 * w.x; m1 += hk1 * w.y;
            }
            size_t yb0 = (size_t)gr0 * Tt * Vv + (size_t)(s + 1) * Vv + gc;
            size_t yb1 = (size_t)gr1 * Tt * Vv + (size_t)(s + 1) * Vv + gc;
            out[yb0] = l0; out[yb0 + 1] = l1;
            out[yb1] = m0; out[yb1 + 1] = m1;
            // per-row argmax over this rank's 64 cols
            float v0 = l0; int i0 = gc; if (l1 > v0) { v0 = l1; i0 = gc + 1; }
            float v1 = m0; int i1 = gc; if (m1 > v1) { v1 = m1; i1 = gc + 1; }
#pragma unroll
            for (int off = 16; off > 0; off >>= 1) {
                float ov = __shfl_down_sync(FULL, v0, off);
                int oi = __shfl_down_sync(FULL, i0, off);
                if (ov > v0 || (ov == v0 && oi < i0)) { v0 = ov; i0 = oi; }
                ov = __shfl_down_sync(FULL, v1, off);
                oi = __shfl_down_sync(FULL, i1, off);
                if (ov > v1 || (ov == v1 && oi < i1)) { v1 = ov; i1 = oi; }
            }
            if (tx == 0) {
                uint32_t lv0 = s2u(&avS[rank * CROWS + lr0]);
                uint32_t li0 = s2u(&aiS[rank * CROWS + lr0]);
#pragma unroll
                for (int rk = 0; rk < CL; rk++) {
                    st_clu_f32(lv0, rk, v0);
                    st_clu_s32(li0, rk, i0);
                    st_clu_f32(lv0 + 4, rk, v1);
                    st_clu_s32(li0 + 4, rk, i1);
                }
            }
        }
        cluster_sync_();
        // combine rank partials (warp 0, lanes 0..15); ranks ascend in col order
        if (tid < CROWS) {
            float bv = avS[tid]; int bi = aiS[tid];
#pragma unroll
            for (int rk = 1; rk < CL; rk++) {
                float vv = avS[rk * CROWS + tid]; int ii = aiS[rk * CROWS + tid];
                if (vv > bv) { bv = vv; bi = ii; }
            }
            biS[tid] = bi;
        }
        __syncthreads();
        // gather next emb
        {
            int row = tid >> 4, c = (tid & 15) * 4;
            int idx = biS[row];
            *(float4*)&emS[row * 64 + c] =
                __ldg((const float4*)&g_WdTb[(size_t)idx * Ee + c]);
        }
        __syncthreads();
    }
}

// ---------------- launch ----------------
extern "C" void kernel_launch(void* const* d_in, const int* in_sizes, int n_in,
                              void* d_out, int out_size) {
    (void)in_sizes; (void)n_in;
    const float* x     = (const float*)d_in[0];
    const int*   xlens = (const int*)  d_in[1];
    const float* We    = (const float*)d_in[2];
    const float* be    = (const float*)d_in[3];
    const float* Wih_e = (const float*)d_in[4];
    const float* Whh_e = (const float*)d_in[5];
    const float* bih_e = (const float*)d_in[6];
    const float* bhh_e = (const float*)d_in[7];
    const float* Wd    = (const float*)d_in[8];
    const float* bd    = (const float*)d_in[9];
    const float* Wih_d = (const float*)d_in[10];
    const float* Whh_d = (const float*)d_in[11];
    const float* bih_d = (const float*)d_in[12];
    const float* bhh_d = (const float*)d_in[13];
    const float* Wo    = (const float*)d_in[14];
    const float* bo    = (const float*)d_in[15];
    float* out = (float*)d_out;

    int write_extra = (out_size >= Bb * Tt * Vv + Bb + Bb * Hh) ? 1 : 0;

    cudaFuncSetAttribute(rec_kernel, cudaFuncAttributeMaxDynamicSharedMemorySize, DSM_BYTES);

    pack_kernel<<<1024, 256>>>(We, Wih_e, Whh_e, bih_e, bhh_e,
                               Wd, bd, Wih_d, Whh_d, bih_d, bhh_d, Wo);
    xe_kernel<<<512, 256>>>(x, be);
    gx_kernel<<<dim3(512, 16), 256>>>();
    emb0_kernel<<<Bb, 64>>>(x, bd);
    init_kernel<<<512, 256>>>(xlens, out, write_extra);
    rec_kernel<<<NB, NT, DSM_BYTES>>>(xlens, bo, out, write_extra);
}